// round 9
// baseline (speedup 1.0000x reference)
#include <cuda_runtime.h>
#include <cstdint>

// Shapes (fixed)
#define B_    64
#define S_    16
#define J_    256
#define QDIM_ 512
#define IDIM_ 512
#define HDIM_ 256
#define BS_   (B_ * S_)    // 1024
#define CHK_  8            // rows per staged chunk
#define NCHK_ (J_ / CHK_)  // 32 chunks

// Scratch (__device__ globals; 16B-aligned: accessed as float4/float2)
__device__ __align__(16) float g_qt[B_ * IDIM_];       // scale*Wk^T(Wq q)   [64, 512]
__device__ __align__(16) float g_pooled[BS_ * IDIM_];  // pooled inputs      [1024, 512]
__device__ __align__(16) float g_WvT[IDIM_ * HDIM_];   // Wv^T               [512, 256]
__device__ int g_mask_u8;                              // 1 = u8 bool mask, 0 = int32

// ---------------- cp.async helpers ----------------
__device__ __forceinline__ void cp_async16(unsigned dst_smem, const void* src) {
    asm volatile("cp.async.cg.shared.global [%0], [%1], 16;"
                 :: "r"(dst_smem), "l"(src));
}
__device__ __forceinline__ void cp_commit() {
    asm volatile("cp.async.commit_group;");
}
__device__ __forceinline__ void cp_wait0() {
    asm volatile("cp.async.wait_group 0;");
}
__device__ __forceinline__ void cp_wait1() {
    asm volatile("cp.async.wait_group 1;");
}

// ---------------------------------------------------------------------------
// Kernel 1 (prologue), grid = 192, block = 256:
//   blocks 0..127  : transpose Wv -> g_WvT (block 0 also detects mask dtype)
//   blocks 128..191: Q[b] = Wq query_b (smem), then qt[b,:] = scale*Wk^T Q[b]
// ---------------------------------------------------------------------------
__global__ __launch_bounds__(256) void prologue_kernel(
    const float*    __restrict__ query,  // [64, 512]
    const float*    __restrict__ Wq,     // [256, 512]
    const float*    __restrict__ Wk,     // [256, 512]
    const float*    __restrict__ Wv,     // [256, 512]
    const unsigned* __restrict__ mask_words)
{
    const int bx  = blockIdx.x;
    const int tid = threadIdx.x;

    if (bx < 128) {
        if (bx == 0) {   // mask dtype detection
            __shared__ int flag;
            if (tid == 0) flag = 0;
            __syncthreads();
            int loc = 0;
            #pragma unroll
            for (int k = 0; k < 4; ++k)
                if (mask_words[tid + 256 * k] > 1u) loc = 1;
            if (loc) flag = 1;
            __syncthreads();
            if (tid == 0) g_mask_u8 = flag;
        }
        __shared__ __align__(16) float tile[32][33];
        const int i0 = (bx & 15) * 32;
        const int h0 = (bx >> 4) * 32;
        const int tx = tid & 31;
        const int ty = tid >> 5;
        #pragma unroll
        for (int r = 0; r < 32; r += 8)
            tile[ty + r][tx] = Wv[(size_t)(h0 + ty + r) * IDIM_ + i0 + tx];
        __syncthreads();
        #pragma unroll
        for (int r = 0; r < 32; r += 8)
            g_WvT[(size_t)(i0 + ty + r) * HDIM_ + h0 + tx] = tile[tx][ty + r];
    } else {
        const int b    = bx - 128;
        const int wid  = tid >> 5;
        const int lane = tid & 31;

        __shared__ __align__(16) float sq[QDIM_];
        __shared__ __align__(16) float sQ[HDIM_];
        sq[tid]       = query[b * QDIM_ + tid];
        sq[tid + 256] = query[b * QDIM_ + tid + 256];
        __syncthreads();

        // register-resident query slice (16 floats per lane)
        float4 qr[4];
        {
            const float4* q4 = reinterpret_cast<const float4*>(sq);
            #pragma unroll
            for (int k = 0; k < 4; ++k) qr[k] = q4[lane + 32 * k];
        }

        // Q: warp wid handles h in [wid*32, wid*32+32), two per step,
        // Wq rows loaded COALESCED across lanes, warp tree-reduce.
        #pragma unroll 2
        for (int t = 0; t < 32; t += 2) {
            const int h = wid * 32 + t;
            const float4* w0 = reinterpret_cast<const float4*>(Wq + (size_t)h * QDIM_);
            const float4* w1 = reinterpret_cast<const float4*>(Wq + (size_t)(h + 1) * QDIM_);
            float s0 = 0.f, s1 = 0.f;
            #pragma unroll
            for (int k = 0; k < 4; ++k) {
                const float4 a = w0[lane + 32 * k];
                const float4 c = w1[lane + 32 * k];
                s0 = fmaf(a.x, qr[k].x, s0); s0 = fmaf(a.y, qr[k].y, s0);
                s0 = fmaf(a.z, qr[k].z, s0); s0 = fmaf(a.w, qr[k].w, s0);
                s1 = fmaf(c.x, qr[k].x, s1); s1 = fmaf(c.y, qr[k].y, s1);
                s1 = fmaf(c.z, qr[k].z, s1); s1 = fmaf(c.w, qr[k].w, s1);
            }
            #pragma unroll
            for (int off = 16; off > 0; off >>= 1) {
                s0 += __shfl_xor_sync(0xffffffffu, s0, off);
                s1 += __shfl_xor_sync(0xffffffffu, s1, off);
            }
            if (lane == 0) { sQ[h] = s0; sQ[h + 1] = s1; }
        }
        __syncthreads();

        // qt[b,i] = scale * sum_h sQ[h] * Wk[h,i]; thread owns i = tid, tid+256.
        float a0[4] = {0.f, 0.f, 0.f, 0.f};
        float a1[4] = {0.f, 0.f, 0.f, 0.f};
        #pragma unroll 4
        for (int h = 0; h < HDIM_; h += 4) {
            #pragma unroll
            for (int k = 0; k < 4; ++k) {
                const float qh = sQ[h + k];
                a0[k] = fmaf(qh, Wk[(size_t)(h + k) * IDIM_ + tid],       a0[k]);
                a1[k] = fmaf(qh, Wk[(size_t)(h + k) * IDIM_ + tid + 256], a1[k]);
            }
        }
        const float scale = 0.0625f;  // 1/sqrt(256)
        g_qt[b * IDIM_ + tid]       = ((a0[0] + a0[1]) + (a0[2] + a0[3])) * scale;
        g_qt[b * IDIM_ + tid + 256] = ((a1[0] + a1[1]) + (a1[2] + a1[3])) * scale;
    }
}

// ---------------------------------------------------------------------------
// Kernel 2: chunked flash softmax-pooling, 3-stage cp.async pipeline.
// CHK=8 (3x16KB smem), 4 CTAs/SM. One block per (b,s). (unchanged from R8)
// ---------------------------------------------------------------------------
__global__ __launch_bounds__(256, 4) void flash_pool_kernel(
    const float* __restrict__ X,     // [64,16,256,512]
    const void*  __restrict__ mask)  // [64,16,256] u8 or i32
{
    const int bs   = blockIdx.x;
    const int b    = bs >> 4;
    const int tid  = threadIdx.x;
    const int wid  = tid >> 5;
    const int lane = tid & 31;

    __shared__ __align__(16) float4 s_stage[3][CHK_ * 128];  // 3 x 16 KB
    __shared__ float s_score[CHK_];

    const float4* x4 = reinterpret_cast<const float4*>(X + (size_t)bs * J_ * IDIM_);
    const int mask_is_u8 = g_mask_u8;
    const uint8_t* mk8  = (const uint8_t*)mask + (size_t)bs * J_;
    const int*     mk32 = (const int*)mask + (size_t)bs * J_;

    float4 qv[4];
    {
        const float4* q4 = reinterpret_cast<const float4*>(g_qt + b * IDIM_);
        #pragma unroll
        for (int k = 0; k < 4; ++k) qv[k] = q4[lane + 32 * k];
    }

    const unsigned sbase = (unsigned)__cvta_generic_to_shared(&s_stage[0][0]);
    const unsigned BUFB  = (unsigned)(CHK_ * 128 * 16);

    #pragma unroll
    for (int u = 0; u < 4; ++u)
        cp_async16(sbase + (unsigned)(tid + 256 * u) * 16u, x4 + tid + 256 * u);
    cp_commit();
    #pragma unroll
    for (int u = 0; u < 4; ++u)
        cp_async16(sbase + BUFB + (unsigned)(tid + 256 * u) * 16u,
                   x4 + CHK_ * 128 + tid + 256 * u);
    cp_commit();

    float m = -1e30f, d = 0.f;
    float px = 0.f, py = 0.f;
    int cur = 0, nxt2 = 2;

    for (int c = 0; c < NCHK_; ++c) {
        if (c == NCHK_ - 1) cp_wait0(); else cp_wait1();
        __syncthreads();

        if (c + 2 < NCHK_) {
            const unsigned sb = sbase + (unsigned)nxt2 * BUFB;
            const float4* src = x4 + (size_t)(c + 2) * (CHK_ * 128);
            #pragma unroll
            for (int u = 0; u < 4; ++u)
                cp_async16(sb + (unsigned)(tid + 256 * u) * 16u, src + tid + 256 * u);
            cp_commit();
        }

        {
            const float4* r0 = &s_stage[cur][wid * 128];
            float s0 = 0.f;
            #pragma unroll
            for (int k = 0; k < 4; ++k) {
                const float4 a = r0[lane + 32 * k];
                s0 = fmaf(a.x, qv[k].x, s0);
                s0 = fmaf(a.y, qv[k].y, s0);
                s0 = fmaf(a.z, qv[k].z, s0);
                s0 = fmaf(a.w, qv[k].w, s0);
            }
            #pragma unroll
            for (int off = 16; off > 0; off >>= 1)
                s0 += __shfl_xor_sync(0xffffffffu, s0, off);
            if (lane == 0) s_score[wid] = s0;
        }
        __syncthreads();

        float sc = -1e30f;
        if (lane < CHK_) {
            sc = s_score[lane];
            const int j = c * CHK_ + lane;
            const bool msk = mask_is_u8 ? (mk8[j] != 0) : (mk32[j] != 0);
            if (msk) sc = -1e30f;
        }
        float mx = sc;
        #pragma unroll
        for (int off = 16; off > 0; off >>= 1)
            mx = fmaxf(mx, __shfl_xor_sync(0xffffffffu, mx, off));
        const float Mn = fmaxf(m, mx);
        const float w  = (lane < CHK_) ? __expf(sc - Mn) : 0.f;
        float ws = w;
        #pragma unroll
        for (int off = 16; off > 0; off >>= 1)
            ws += __shfl_xor_sync(0xffffffffu, ws, off);
        const float f = __expf(m - Mn);
        m = Mn;
        d = fmaf(d, f, ws);

        px *= f;  py *= f;
        const float2* st2 = reinterpret_cast<const float2*>(&s_stage[cur][0]);
        #pragma unroll
        for (int r = 0; r < CHK_; ++r) {
            const float  wr = __shfl_sync(0xffffffffu, w, r);
            const float2 xv = st2[r * 256 + tid];
            px = fmaf(wr, xv.x, px);
            py = fmaf(wr, xv.y, py);
        }

        cur  = (cur == 2)  ? 0 : cur + 1;
        nxt2 = (nxt2 == 2) ? 0 : nxt2 + 1;
    }

    const float inv = 1.f / d;
    reinterpret_cast<float2*>(g_pooled + (size_t)bs * IDIM_)[tid] =
        make_float2(px * inv, py * inv);
}

// ---------------------------------------------------------------------------
// Kernel 3: smem-tiled GEMM  out[1024,256] = pooled[1024,512] @ WvT[512,256]
// BM=32, BN=64, BK=32; 256 threads, 2x4 register tile; 128 blocks (~2/SM).
// ---------------------------------------------------------------------------
#define BM_ 32
#define BN_ 64
#define BK_ 32
__global__ __launch_bounds__(256) void epilogue_kernel(float* __restrict__ out)
{
    const int tid = threadIdx.x;
    const int h0  = blockIdx.x * BN_;   // 0..3
    const int m0  = blockIdx.y * BM_;   // 0..31
    const int tx  = tid & 15;           // n-tile (4 cols each)
    const int ty  = tid >> 4;           // m-tile (2 rows each)

    __shared__ float sA[BM_][BK_ + 1];              // 4.1 KB, padded
    __shared__ __align__(16) float sB[BK_][BN_];    // 8 KB

    float acc[2][4];
    #pragma unroll
    for (int i = 0; i < 2; ++i)
        #pragma unroll
        for (int j = 0; j < 4; ++j) acc[i][j] = 0.f;

    const int ar = tid >> 3;          // 0..31 (m row)
    const int ac = (tid & 7) * 4;     // k col (float4)
    const int br = tid >> 4;          // 0..15 (k row)
    const int bc = (tid & 15) * 4;    // n col (float4)

    for (int k0 = 0; k0 < IDIM_; k0 += BK_) {
        {   // A tile 32x32: 1 float4/thread, coalesced
            const float4 v = *reinterpret_cast<const float4*>(
                g_pooled + (size_t)(m0 + ar) * IDIM_ + k0 + ac);
            sA[ar][ac + 0] = v.x;  sA[ar][ac + 1] = v.y;
            sA[ar][ac + 2] = v.z;  sA[ar][ac + 3] = v.w;
        }
        #pragma unroll
        for (int r = 0; r < 2; ++r) {   // B tile 32x64: 2 float4/thread
            const int kk = br + 16 * r;
            *reinterpret_cast<float4*>(&sB[kk][bc]) =
                *reinterpret_cast<const float4*>(
                    g_WvT + (size_t)(k0 + kk) * HDIM_ + h0 + bc);
        }
        __syncthreads();

        #pragma unroll
        for (int kk = 0; kk < BK_; ++kk) {
            const float a0 = sA[ty * 2 + 0][kk];
            const float a1 = sA[ty * 2 + 1][kk];
            const float4 bv = *reinterpret_cast<const float4*>(&sB[kk][tx * 4]);
            acc[0][0] = fmaf(a0, bv.x, acc[0][0]);
            acc[0][1] = fmaf(a0, bv.y, acc[0][1]);
            acc[0][2] = fmaf(a0, bv.z, acc[0][2]);
            acc[0][3] = fmaf(a0, bv.w, acc[0][3]);
            acc[1][0] = fmaf(a1, bv.x, acc[1][0]);
            acc[1][1] = fmaf(a1, bv.y, acc[1][1]);
            acc[1][2] = fmaf(a1, bv.z, acc[1][2]);
            acc[1][3] = fmaf(a1, bv.w, acc[1][3]);
        }
        __syncthreads();
    }

    #pragma unroll
    for (int i = 0; i < 2; ++i) {
        const float4 v = make_float4(acc[i][0], acc[i][1], acc[i][2], acc[i][3]);
        *reinterpret_cast<float4*>(
            out + (size_t)(m0 + ty * 2 + i) * HDIM_ + h0 + tx * 4) = v;
    }
}

// ---------------------------------------------------------------------------
// Launch.  Inputs: query, other_semesters, mask, Wq, Wk, Wv
// ---------------------------------------------------------------------------
extern "C" void kernel_launch(void* const* d_in, const int* in_sizes, int n_in,
                              void* d_out, int out_size)
{
    const float* query = (const float*)d_in[0];
    const float* X     = (const float*)d_in[1];
    const void*  mask  = d_in[2];
    const float* Wq    = (const float*)d_in[3];
    const float* Wk    = (const float*)d_in[4];
    const float* Wv    = (const float*)d_in[5];
    float*       out   = (float*)d_out;

    prologue_kernel<<<192, 256>>>(query, Wq, Wk, Wv, (const unsigned*)mask);
    flash_pool_kernel<<<BS_, 256>>>(X, mask);
    epilogue_kernel<<<dim3(HDIM_ / BN_, BS_ / BM_), 256>>>(out);
}

// round 10
// speedup vs baseline: 1.0803x; 1.0803x over previous
#include <cuda_runtime.h>
#include <cstdint>

// Shapes (fixed)
#define B_    64
#define S_    16
#define J_    256
#define QDIM_ 512
#define IDIM_ 512
#define HDIM_ 256
#define BS_   (B_ * S_)    // 1024
#define CHK_  8            // rows per staged chunk
#define NCHK_ (J_ / CHK_)  // 32 chunks

// Scratch (__device__ globals; 16B-aligned: accessed as float4/float2)
__device__ __align__(16) float g_Q[B_ * HDIM_];        // Wq q               [64, 256]
__device__ __align__(16) float g_qt[B_ * IDIM_];       // scale*Wk^T(Wq q)   [64, 512]
__device__ __align__(16) float g_pooled[BS_ * IDIM_];  // pooled inputs      [1024, 512]
__device__ __align__(16) float g_WvT[IDIM_ * HDIM_];   // Wv^T               [512, 256]
__device__ int g_mask_u8;                              // 1 = u8 bool mask, 0 = int32

// ---------------- cp.async helpers ----------------
__device__ __forceinline__ void cp_async16(unsigned dst_smem, const void* src) {
    asm volatile("cp.async.cg.shared.global [%0], [%1], 16;"
                 :: "r"(dst_smem), "l"(src));
}
__device__ __forceinline__ void cp_commit() {
    asm volatile("cp.async.commit_group;");
}
__device__ __forceinline__ void cp_wait0() {
    asm volatile("cp.async.wait_group 0;");
}
__device__ __forceinline__ void cp_wait1() {
    asm volatile("cp.async.wait_group 1;");
}

// ---------------------------------------------------------------------------
// Kernel 1 (prologue), grid = 192, block = 256:
//   blocks 0..127  : transpose Wv -> g_WvT (block 0 also detects mask dtype)
//   blocks 128..191: Q[b,h] = sum_q query[b,q]*Wq[h,q]  (warp-per-2h, coalesced)
// ---------------------------------------------------------------------------
__global__ __launch_bounds__(256) void prologue_kernel(
    const float*    __restrict__ query,  // [64, 512]
    const float*    __restrict__ Wq,     // [256, 512]
    const float*    __restrict__ Wv,     // [256, 512]
    const unsigned* __restrict__ mask_words)
{
    const int bx  = blockIdx.x;
    const int tid = threadIdx.x;

    if (bx < 128) {
        if (bx == 0) {   // mask dtype detection
            __shared__ int flag;
            if (tid == 0) flag = 0;
            __syncthreads();
            int loc = 0;
            #pragma unroll
            for (int k = 0; k < 4; ++k)
                if (mask_words[tid + 256 * k] > 1u) loc = 1;
            if (loc) flag = 1;
            __syncthreads();
            if (tid == 0) g_mask_u8 = flag;
        }
        __shared__ __align__(16) float tile[32][33];
        const int i0 = (bx & 15) * 32;
        const int h0 = (bx >> 4) * 32;
        const int tx = tid & 31;
        const int ty = tid >> 5;
        #pragma unroll
        for (int r = 0; r < 32; r += 8)
            tile[ty + r][tx] = Wv[(size_t)(h0 + ty + r) * IDIM_ + i0 + tx];
        __syncthreads();
        #pragma unroll
        for (int r = 0; r < 32; r += 8)
            g_WvT[(size_t)(i0 + ty + r) * HDIM_ + h0 + tx] = tile[tx][ty + r];
    } else {
        const int b    = bx - 128;
        const int wid  = tid >> 5;
        const int lane = tid & 31;

        __shared__ __align__(16) float sq[QDIM_];
        sq[tid]       = query[b * QDIM_ + tid];
        sq[tid + 256] = query[b * QDIM_ + tid + 256];
        __syncthreads();

        float4 qr[4];
        {
            const float4* q4 = reinterpret_cast<const float4*>(sq);
            #pragma unroll
            for (int k = 0; k < 4; ++k) qr[k] = q4[lane + 32 * k];
        }

        #pragma unroll 2
        for (int t = 0; t < 32; t += 2) {
            const int h = wid * 32 + t;
            const float4* w0 = reinterpret_cast<const float4*>(Wq + (size_t)h * QDIM_);
            const float4* w1 = reinterpret_cast<const float4*>(Wq + (size_t)(h + 1) * QDIM_);
            float s0 = 0.f, s1 = 0.f;
            #pragma unroll
            for (int k = 0; k < 4; ++k) {
                const float4 a = w0[lane + 32 * k];   // coalesced across lanes
                const float4 c = w1[lane + 32 * k];
                s0 = fmaf(a.x, qr[k].x, s0); s0 = fmaf(a.y, qr[k].y, s0);
                s0 = fmaf(a.z, qr[k].z, s0); s0 = fmaf(a.w, qr[k].w, s0);
                s1 = fmaf(c.x, qr[k].x, s1); s1 = fmaf(c.y, qr[k].y, s1);
                s1 = fmaf(c.z, qr[k].z, s1); s1 = fmaf(c.w, qr[k].w, s1);
            }
            #pragma unroll
            for (int off = 16; off > 0; off >>= 1) {
                s0 += __shfl_xor_sync(0xffffffffu, s0, off);
                s1 += __shfl_xor_sync(0xffffffffu, s1, off);
            }
            if (lane == 0) {
                g_Q[b * HDIM_ + h]     = s0;
                g_Q[b * HDIM_ + h + 1] = s1;
            }
        }
    }
}

// ---------------------------------------------------------------------------
// Kernel 1b: qt[b,i] = scale * sum_h Q[b,h] * Wk[h,i]
// grid = 256 (b x i-quarter), 256 threads: thread -> (col = tid&127, h-half =
// tid>>7). Two threads per column, each sums 128 h, combine via smem.
// ---------------------------------------------------------------------------
__global__ __launch_bounds__(256) void qt_kernel(
    const float* __restrict__ Wk)    // [256, 512]
{
    const int b    = blockIdx.x >> 2;
    const int i0   = (blockIdx.x & 3) * 128;
    const int tid  = threadIdx.x;
    const int col  = i0 + (tid & 127);
    const int hh   = tid >> 7;          // 0 or 1

    __shared__ __align__(16) float sQ[HDIM_];
    __shared__ float s_part[256];
    sQ[tid] = g_Q[b * HDIM_ + tid];
    __syncthreads();

    float a[8];
    #pragma unroll
    for (int k = 0; k < 8; ++k) a[k] = 0.f;

    const int hbase = hh * 128;
    #pragma unroll 4
    for (int h = 0; h < 128; h += 8) {
        #pragma unroll
        for (int k = 0; k < 8; ++k)
            a[k] = fmaf(sQ[hbase + h + k],
                        Wk[(size_t)(hbase + h + k) * IDIM_ + col], a[k]);
    }
    s_part[tid] = ((a[0] + a[1]) + (a[2] + a[3])) + ((a[4] + a[5]) + (a[6] + a[7]));
    __syncthreads();

    if (tid < 128) {
        const float scale = 0.0625f;  // 1/sqrt(256)
        g_qt[b * IDIM_ + i0 + tid] = (s_part[tid] + s_part[tid + 128]) * scale;
    }
}

// ---------------------------------------------------------------------------
// Kernel 2: chunked flash softmax-pooling, 3-stage cp.async pipeline.
// CHK=8 (3x16KB smem), 4 CTAs/SM. One block per (b,s). (unchanged)
// ---------------------------------------------------------------------------
__global__ __launch_bounds__(256, 4) void flash_pool_kernel(
    const float* __restrict__ X,     // [64,16,256,512]
    const void*  __restrict__ mask)  // [64,16,256] u8 or i32
{
    const int bs   = blockIdx.x;
    const int b    = bs >> 4;
    const int tid  = threadIdx.x;
    const int wid  = tid >> 5;
    const int lane = tid & 31;

    __shared__ __align__(16) float4 s_stage[3][CHK_ * 128];  // 3 x 16 KB
    __shared__ float s_score[CHK_];

    const float4* x4 = reinterpret_cast<const float4*>(X + (size_t)bs * J_ * IDIM_);
    const int mask_is_u8 = g_mask_u8;
    const uint8_t* mk8  = (const uint8_t*)mask + (size_t)bs * J_;
    const int*     mk32 = (const int*)mask + (size_t)bs * J_;

    float4 qv[4];
    {
        const float4* q4 = reinterpret_cast<const float4*>(g_qt + b * IDIM_);
        #pragma unroll
        for (int k = 0; k < 4; ++k) qv[k] = q4[lane + 32 * k];
    }

    const unsigned sbase = (unsigned)__cvta_generic_to_shared(&s_stage[0][0]);
    const unsigned BUFB  = (unsigned)(CHK_ * 128 * 16);

    #pragma unroll
    for (int u = 0; u < 4; ++u)
        cp_async16(sbase + (unsigned)(tid + 256 * u) * 16u, x4 + tid + 256 * u);
    cp_commit();
    #pragma unroll
    for (int u = 0; u < 4; ++u)
        cp_async16(sbase + BUFB + (unsigned)(tid + 256 * u) * 16u,
                   x4 + CHK_ * 128 + tid + 256 * u);
    cp_commit();

    float m = -1e30f, d = 0.f;
    float px = 0.f, py = 0.f;
    int cur = 0, nxt2 = 2;

    for (int c = 0; c < NCHK_; ++c) {
        if (c == NCHK_ - 1) cp_wait0(); else cp_wait1();
        __syncthreads();

        if (c + 2 < NCHK_) {
            const unsigned sb = sbase + (unsigned)nxt2 * BUFB;
            const float4* src = x4 + (size_t)(c + 2) * (CHK_ * 128);
            #pragma unroll
            for (int u = 0; u < 4; ++u)
                cp_async16(sb + (unsigned)(tid + 256 * u) * 16u, src + tid + 256 * u);
            cp_commit();
        }

        {
            const float4* r0 = &s_stage[cur][wid * 128];
            float s0 = 0.f;
            #pragma unroll
            for (int k = 0; k < 4; ++k) {
                const float4 a = r0[lane + 32 * k];
                s0 = fmaf(a.x, qv[k].x, s0);
                s0 = fmaf(a.y, qv[k].y, s0);
                s0 = fmaf(a.z, qv[k].z, s0);
                s0 = fmaf(a.w, qv[k].w, s0);
            }
            #pragma unroll
            for (int off = 16; off > 0; off >>= 1)
                s0 += __shfl_xor_sync(0xffffffffu, s0, off);
            if (lane == 0) s_score[wid] = s0;
        }
        __syncthreads();

        float sc = -1e30f;
        if (lane < CHK_) {
            sc = s_score[lane];
            const int j = c * CHK_ + lane;
            const bool msk = mask_is_u8 ? (mk8[j] != 0) : (mk32[j] != 0);
            if (msk) sc = -1e30f;
        }
        float mx = sc;
        #pragma unroll
        for (int off = 16; off > 0; off >>= 1)
            mx = fmaxf(mx, __shfl_xor_sync(0xffffffffu, mx, off));
        const float Mn = fmaxf(m, mx);
        const float w  = (lane < CHK_) ? __expf(sc - Mn) : 0.f;
        float ws = w;
        #pragma unroll
        for (int off = 16; off > 0; off >>= 1)
            ws += __shfl_xor_sync(0xffffffffu, ws, off);
        const float f = __expf(m - Mn);
        m = Mn;
        d = fmaf(d, f, ws);

        px *= f;  py *= f;
        const float2* st2 = reinterpret_cast<const float2*>(&s_stage[cur][0]);
        #pragma unroll
        for (int r = 0; r < CHK_; ++r) {
            const float  wr = __shfl_sync(0xffffffffu, w, r);
            const float2 xv = st2[r * 256 + tid];
            px = fmaf(wr, xv.x, px);
            py = fmaf(wr, xv.y, py);
        }

        cur  = (cur == 2)  ? 0 : cur + 1;
        nxt2 = (nxt2 == 2) ? 0 : nxt2 + 1;
    }

    const float inv = 1.f / d;
    reinterpret_cast<float2*>(g_pooled + (size_t)bs * IDIM_)[tid] =
        make_float2(px * inv, py * inv);
}

// ---------------------------------------------------------------------------
// Kernel 3: smem-tiled GEMM  out[1024,256] = pooled[1024,512] @ WvT[512,256]
// BM=32, BN=64, BK=32; 256 threads, 2x4 register tile; 128 blocks. (unchanged)
// ---------------------------------------------------------------------------
#define BM_ 32
#define BN_ 64
#define BK_ 32
__global__ __launch_bounds__(256) void epilogue_kernel(float* __restrict__ out)
{
    const int tid = threadIdx.x;
    const int h0  = blockIdx.x * BN_;
    const int m0  = blockIdx.y * BM_;
    const int tx  = tid & 15;
    const int ty  = tid >> 4;

    __shared__ float sA[BM_][BK_ + 1];
    __shared__ __align__(16) float sB[BK_][BN_];

    float acc[2][4];
    #pragma unroll
    for (int i = 0; i < 2; ++i)
        #pragma unroll
        for (int j = 0; j < 4; ++j) acc[i][j] = 0.f;

    const int ar = tid >> 3;
    const int ac = (tid & 7) * 4;
    const int br = tid >> 4;
    const int bc = (tid & 15) * 4;

    for (int k0 = 0; k0 < IDIM_; k0 += BK_) {
        {
            const float4 v = *reinterpret_cast<const float4*>(
                g_pooled + (size_t)(m0 + ar) * IDIM_ + k0 + ac);
            sA[ar][ac + 0] = v.x;  sA[ar][ac + 1] = v.y;
            sA[ar][ac + 2] = v.z;  sA[ar][ac + 3] = v.w;
        }
        #pragma unroll
        for (int r = 0; r < 2; ++r) {
            const int kk = br + 16 * r;
            *reinterpret_cast<float4*>(&sB[kk][bc]) =
                *reinterpret_cast<const float4*>(
                    g_WvT + (size_t)(k0 + kk) * HDIM_ + h0 + bc);
        }
        __syncthreads();

        #pragma unroll
        for (int kk = 0; kk < BK_; ++kk) {
            const float a0 = sA[ty * 2 + 0][kk];
            const float a1 = sA[ty * 2 + 1][kk];
            const float4 bv = *reinterpret_cast<const float4*>(&sB[kk][tx * 4]);
            acc[0][0] = fmaf(a0, bv.x, acc[0][0]);
            acc[0][1] = fmaf(a0, bv.y, acc[0][1]);
            acc[0][2] = fmaf(a0, bv.z, acc[0][2]);
            acc[0][3] = fmaf(a0, bv.w, acc[0][3]);
            acc[1][0] = fmaf(a1, bv.x, acc[1][0]);
            acc[1][1] = fmaf(a1, bv.y, acc[1][1]);
            acc[1][2] = fmaf(a1, bv.z, acc[1][2]);
            acc[1][3] = fmaf(a1, bv.w, acc[1][3]);
        }
        __syncthreads();
    }

    #pragma unroll
    for (int i = 0; i < 2; ++i) {
        const float4 v = make_float4(acc[i][0], acc[i][1], acc[i][2], acc[i][3]);
        *reinterpret_cast<float4*>(
            out + (size_t)(m0 + ty * 2 + i) * HDIM_ + h0 + tx * 4) = v;
    }
}

// ---------------------------------------------------------------------------
// Launch.  Inputs: query, other_semesters, mask, Wq, Wk, Wv
// ---------------------------------------------------------------------------
extern "C" void kernel_launch(void* const* d_in, const int* in_sizes, int n_in,
                              void* d_out, int out_size)
{
    const float* query = (const float*)d_in[0];
    const float* X     = (const float*)d_in[1];
    const void*  mask  = d_in[2];
    const float* Wq    = (const float*)d_in[3];
    const float* Wk    = (const float*)d_in[4];
    const float* Wv    = (const float*)d_in[5];
    float*       out   = (float*)d_out;

    prologue_kernel<<<192, 256>>>(query, Wq, Wv, (const unsigned*)mask);
    qt_kernel<<<256, 256>>>(Wk);
    flash_pool_kernel<<<BS_, 256>>>(X, mask);
    epilogue_kernel<<<dim3(HDIM_ / BN_, BS_ / BM_), 256>>>(out);
}